// round 14
// baseline (speedup 1.0000x reference)
#include <cuda_runtime.h>
#include <cuda_bf16.h>
#include <cstdint>
#include <math.h>

#define NTOK 32768          // B * C * T = 8 * 64 * 64
#define DM   768
#define DQKV 2304
#define DFC  3072

// ---------------- scratch (device globals; no allocations) ----------------
// Device globals are zero-initialized at module load; amax slots are updated only
// via atomicMax with input-determined values, so graph replay is idempotent.
__device__ __align__(16) float  g_f[(size_t)NTOK * DM];
__device__ __align__(16) float  g_qkv[(size_t)NTOK * DQKV];
__device__ __align__(16) float  g_x2[(size_t)NTOK * DM];
__device__ __align__(16) float  g_fc1[(size_t)NTOK * DFC];
__device__ __align__(16) __nv_bfloat16 g_qb[(size_t)NTOK * DM];     // quantized act as bf16
__device__ __align__(16) __nv_bfloat16 g_fc1q[(size_t)NTOK * DFC];
__device__ __align__(16) __nv_bfloat16 g_wqkv[DQKV * DM];
__device__ __align__(16) __nv_bfloat16 g_wproj[DM * DM];
__device__ __align__(16) __nv_bfloat16 g_wfc1[DFC * DM];
__device__ __align__(16) __nv_bfloat16 g_wfc2[DM * DFC];
__device__ __align__(16) float  g_amax[16];        // 4..7 weight amax
__device__ __align__(16) float  g_slots[4 * 2048]; // spread amax slots (32 used, stride 64)

__device__ __forceinline__ void atomicMaxF(float* a, float v) {
    atomicMax(reinterpret_cast<unsigned int*>(a), __float_as_uint(v)); // v >= 0
}
__device__ __forceinline__ uint32_t smem_u32(const void* p) {
    return (uint32_t)__cvta_generic_to_shared(p);
}
__device__ __forceinline__ void cp16(uint32_t dst, const void* src) {
    asm volatile("cp.async.cg.shared.global [%0], [%1], 16;\n" :: "r"(dst), "l"(src));
}
__device__ __forceinline__ void ldsm4(uint32_t a, int* r) {
    asm volatile("ldmatrix.sync.aligned.m8n8.x4.shared.b16 {%0,%1,%2,%3}, [%4];"
                 : "=r"(r[0]), "=r"(r[1]), "=r"(r[2]), "=r"(r[3]) : "r"(a));
}
__device__ __forceinline__ void mma_bf16(float* c, const int* a, int b0, int b1) {
    asm volatile(
        "mma.sync.aligned.m16n8k16.row.col.f32.bf16.bf16.f32 "
        "{%0,%1,%2,%3}, {%4,%5,%6,%7}, {%8,%9}, {%0,%1,%2,%3};\n"
        : "+f"(c[0]), "+f"(c[1]), "+f"(c[2]), "+f"(c[3])
        : "r"(a[0]), "r"(a[1]), "r"(a[2]), "r"(a[3]), "r"(b0), "r"(b1));
}

// packed f32x2 helpers (Blackwell): component-wise fma.rn, bit-identical per lane
__device__ __forceinline__ uint64_t pack2(float lo, float hi) {
    uint64_t r; asm("mov.b64 %0, {%1, %2};" : "=l"(r) : "f"(lo), "f"(hi)); return r;
}
__device__ __forceinline__ void unpack2(uint64_t v, float& lo, float& hi) {
    asm("mov.b64 {%0, %1}, %2;" : "=f"(lo), "=f"(hi) : "l"(v));
}
__device__ __forceinline__ void ffma2(uint64_t& c, uint64_t a, uint64_t b) {
    asm("fma.rn.f32x2 %0, %1, %2, %0;" : "+l"(c) : "l"(a), "l"(b));
}

// max over n slot entries (stride 64 floats); n=1 for plain scalar
__device__ __forceinline__ float amax_get(const float* __restrict__ p, int n) {
    float m = p[0];
    for (int i = 1; i < n; i++) m = fmaxf(m, p[i * 64]);
    return fmaxf(m, 1e-8f);
}

// quantize two floats -> packed bf16x2 (values are small ints, conversion exact)
__device__ __forceinline__ uint32_t q2bf(float a, float b, float s) {
    float ra = fminf(fmaxf(rintf(__fdiv_rn(a, s)), -128.0f), 127.0f);
    float rb = fminf(fmaxf(rintf(__fdiv_rn(b, s)), -128.0f), 127.0f);
    uint32_t r;
    asm("cvt.rn.bf16x2.f32 %0, %1, %2;" : "=r"(r) : "f"(rb), "f"(ra)); // hi=rb, lo=ra
    return r;
}

// ---------------- weight absmax (segmented, 2x float4 per iter) ----------------
__global__ __launch_bounds__(256) void absmax_w_k(
    const float* __restrict__ w0, const float* __restrict__ w1,
    const float* __restrict__ w2, const float* __restrict__ w3, float* __restrict__ amax)
{
    const float* w; int n8;
    switch (blockIdx.y) {
        case 0: w = w0; n8 = DQKV * DM / 8; break;
        case 1: w = w1; n8 = DM * DM / 8;   break;
        case 2: w = w2; n8 = DFC * DM / 8;  break;
        default: w = w3; n8 = DM * DFC / 8; break;
    }
    float m = 0.0f;
#pragma unroll 2
    for (int i = blockIdx.x * 256 + threadIdx.x; i < n8; i += gridDim.x * 256) {
        float4 a = reinterpret_cast<const float4*>(w)[2 * i];
        float4 b = reinterpret_cast<const float4*>(w)[2 * i + 1];
        m = fmaxf(m, fmaxf(fmaxf(fabsf(a.x), fabsf(a.y)), fmaxf(fabsf(a.z), fabsf(a.w))));
        m = fmaxf(m, fmaxf(fmaxf(fabsf(b.x), fabsf(b.y)), fmaxf(fabsf(b.z), fabsf(b.w))));
    }
#pragma unroll
    for (int o = 16; o > 0; o >>= 1) m = fmaxf(m, __shfl_xor_sync(0xffffffffu, m, o));
    __shared__ float sm[8];
    if ((threadIdx.x & 31) == 0) sm[threadIdx.x >> 5] = m;
    __syncthreads();
    if (threadIdx.x == 0) {
        float t = sm[0];
#pragma unroll
        for (int k = 1; k < 8; k++) t = fmaxf(t, sm[k]);
        atomicMaxF(&amax[4 + blockIdx.y], t);
    }
}

// ---------------- weight quantize (segmented, 2x float4 -> uint4) ----------------
__global__ __launch_bounds__(256) void quant_w_k(
    const float* __restrict__ w0, const float* __restrict__ w1,
    const float* __restrict__ w2, const float* __restrict__ w3,
    __nv_bfloat16* __restrict__ q0, __nv_bfloat16* __restrict__ q1,
    __nv_bfloat16* __restrict__ q2, __nv_bfloat16* __restrict__ q3,
    const float* __restrict__ amax)
{
    const float* w; __nv_bfloat16* q; int n8;
    switch (blockIdx.y) {
        case 0: w = w0; q = q0; n8 = DQKV * DM / 8; break;
        case 1: w = w1; q = q1; n8 = DM * DM / 8;   break;
        case 2: w = w2; q = q2; n8 = DFC * DM / 8;  break;
        default: w = w3; q = q3; n8 = DM * DFC / 8; break;
    }
    float s = __fdiv_rn(amax_get(&amax[4 + blockIdx.y], 1), 127.0f);
#pragma unroll 2
    for (int i = blockIdx.x * 256 + threadIdx.x; i < n8; i += gridDim.x * 256) {
        float4 a = reinterpret_cast<const float4*>(w)[2 * i];
        float4 b = reinterpret_cast<const float4*>(w)[2 * i + 1];
        uint4 p;
        p.x = q2bf(a.x, a.y, s);
        p.y = q2bf(a.z, a.w, s);
        p.z = q2bf(b.x, b.y, s);
        p.w = q2bf(b.z, b.w, s);
        reinterpret_cast<uint4*>(q)[i] = p;
    }
}

// ---------------- activation quantize (2x float4 -> uint4, slot-reduced scale) ----
__global__ __launch_bounds__(256) void quant_a_k(const float* __restrict__ x,
                                                 __nv_bfloat16* __restrict__ q, int n8,
                                                 const float* __restrict__ slots) {
    float s = __fdiv_rn(amax_get(slots, 32), 127.0f);
#pragma unroll 4
    for (int i = blockIdx.x * 256 + threadIdx.x; i < n8; i += gridDim.x * 256) {
        float4 a = reinterpret_cast<const float4*>(x)[2 * i];
        float4 b = reinterpret_cast<const float4*>(x)[2 * i + 1];
        uint4 p;
        p.x = q2bf(a.x, a.y, s);
        p.y = q2bf(a.z, a.w, s);
        p.z = q2bf(b.x, b.y, s);
        p.w = q2bf(b.z, b.w, s);
        reinterpret_cast<uint4*>(q)[i] = p;
    }
}

// ---------------- layernorm + fused absmax (192 threads, float4) ----------------
__global__ __launch_bounds__(192) void ln_k(const float* __restrict__ x,
                                            const float* __restrict__ g,
                                            const float* __restrict__ b,
                                            float* __restrict__ out,
                                            float* __restrict__ slot) {
    __shared__ float sm[6];
    __shared__ float bc[2];
    int row = blockIdx.x, tid = threadIdx.x;
    int lane = tid & 31, wid = tid >> 5;   // 6 warps
    float4 v = reinterpret_cast<const float4*>(x + (size_t)row * DM)[tid];

    float s = v.x + v.y + v.z + v.w;
#pragma unroll
    for (int o = 16; o > 0; o >>= 1) s += __shfl_xor_sync(0xffffffffu, s, o);
    if (lane == 0) sm[wid] = s;
    __syncthreads();
    if (wid == 0) {
        float t = (lane < 6) ? sm[lane] : 0.0f;
#pragma unroll
        for (int o = 4; o > 0; o >>= 1) t += __shfl_xor_sync(0xffffffffu, t, o);
        if (lane == 0) bc[0] = t * (1.0f / 768.0f);
    }
    __syncthreads();
    float mean = bc[0];
    float4 d = make_float4(v.x - mean, v.y - mean, v.z - mean, v.w - mean);
    float ss = d.x * d.x + d.y * d.y + d.z * d.z + d.w * d.w;
#pragma unroll
    for (int o = 16; o > 0; o >>= 1) ss += __shfl_xor_sync(0xffffffffu, ss, o);
    if (lane == 0) sm[wid] = ss;
    __syncthreads();
    if (wid == 0) {
        float t = (lane < 6) ? sm[lane] : 0.0f;
#pragma unroll
        for (int o = 4; o > 0; o >>= 1) t += __shfl_xor_sync(0xffffffffu, t, o);
        if (lane == 0) bc[1] = __frsqrt_rn(t * (1.0f / 768.0f) + 1e-5f);
    }
    __syncthreads();
    float rs = bc[1];
    float4 gg = reinterpret_cast<const float4*>(g)[tid];
    float4 bb = reinterpret_cast<const float4*>(b)[tid];
    float4 o4;
    o4.x = d.x * rs * gg.x + bb.x;
    o4.y = d.y * rs * gg.y + bb.y;
    o4.z = d.z * rs * gg.z + bb.z;
    o4.w = d.w * rs * gg.w + bb.w;
    reinterpret_cast<float4*>(out + (size_t)row * DM)[tid] = o4;

    float lm = fmaxf(fmaxf(fabsf(o4.x), fabsf(o4.y)), fmaxf(fabsf(o4.z), fabsf(o4.w)));
#pragma unroll
    for (int o = 16; o > 0; o >>= 1) lm = fmaxf(lm, __shfl_xor_sync(0xffffffffu, lm, o));
    if (lane == 0) sm[wid] = lm;
    __syncthreads();
    if (tid == 0) {
        float t = sm[0];
#pragma unroll
        for (int k = 1; k < 6; k++) t = fmaxf(t, sm[k]);
        atomicMaxF(slot + (row & 31) * 64, t);
    }
}

// ---------------- bf16 HMMA GEMM, C = A[M,K] * B[N,K]^T ----------------
// Block 128x128, BK=64 (128B rows, XOR swizzle on 16B chunks), 3-stage cp.async
// with a single __syncthreads per k-iteration. Warp grid 4(M) x 2(N); warp tile
// 32x64 via mma.m16n8k16.bf16 (fp32 accum).
// EPI: 0 = bias, 1 = bias + residual, 2 = bias + exact GELU + fused absmax
template<int EPI>
__global__ __launch_bounds__(256, 2) void gemm_bf16_k(
    const __nv_bfloat16* __restrict__ A, const __nv_bfloat16* __restrict__ B,
    int M, int N, int K,
    const float* __restrict__ amaxA, int nA,
    const float* __restrict__ amaxB, int nB,
    const float* __restrict__ bias, const float* __restrict__ res,
    float* __restrict__ C, float* __restrict__ gmax)
{
    extern __shared__ __align__(1024) char smem[];   // 3 stages x (A 16KB + B 16KB)
    const uint32_t sbase = smem_u32(smem);
    const int tid  = threadIdx.x;
    const int lane = tid & 31, warp = tid >> 5;
    const int wm = warp & 3, wn = warp >> 2;
    const int m0 = blockIdx.y * 128, n0 = blockIdx.x * 128;
    const int gid = lane >> 2, tig = lane & 3;

    float acc[2][8][4];
#pragma unroll
    for (int mi = 0; mi < 2; mi++)
#pragma unroll
        for (int nj = 0; nj < 8; nj++)
#pragma unroll
            for (int r = 0; r < 4; r++) acc[mi][nj][r] = 0.0f;

    // global->smem mapping: thread t handles row t>>1, chunks (t&1)*4 .. +3 (16B each)
    const int lrow = tid >> 1, lcb = (tid & 1) * 4;
    const char* gA = (const char*)(A + (size_t)(m0 + lrow) * K) + lcb * 16;
    const char* gB = (const char*)(B + (size_t)(n0 + lrow) * K) + lcb * 16;
    uint32_t dst[4];
#pragma unroll
    for (int c = 0; c < 4; c++)
        dst[c] = lrow * 128 + (((lcb + c) ^ (lrow & 7)) << 4);

    // ldmatrix lane addressing (row-dependent swizzle s = row & 7 = lane & 7)
    const int s7 = lane & 7;
    uint32_t koff[4];
#pragma unroll
    for (int ks = 0; ks < 4; ks++) koff[ks] = ((ks * 2) ^ (s7 & 6)) << 4;
    const int rowA0 = wm * 32 + s7 + ((lane >> 3) & 1) * 8;
    const uint32_t aAb = rowA0 * 128 + (((((lane >> 4) & 1)) ^ (s7 & 1)) << 4);
    const int rowB0 = wn * 64 + s7 + ((lane >> 4) & 1) * 8;
    const uint32_t aBb = 16384 + rowB0 * 128 + (((((lane >> 3) & 1)) ^ (s7 & 1)) << 4);

    const int KT = K >> 6;   // >= 12 always

#define GISSUE(stg, ktile) do {                                          \
        const uint32_t so_ = (uint32_t)(stg) * 32768u;                   \
        const char* pA_ = gA + (size_t)(ktile) * 128;                    \
        const char* pB_ = gB + (size_t)(ktile) * 128;                    \
        _Pragma("unroll")                                                \
        for (int c_ = 0; c_ < 4; c_++) {                                 \
            cp16(sbase + so_ + dst[c_], pA_ + c_ * 16);                  \
            cp16(sbase + so_ + 16384 + dst[c_], pB_ + c_ * 16);          \
        }                                                                \
        asm volatile("cp.async.commit_group;\n");                        \
    } while (0)

    // prologue: stages 0 and 1 (groups 0, 1)
    GISSUE(0, 0);
    GISSUE(1, 1);

    int s_cur = 0, s_nxt = 2;
    for (int kt = 0; kt < KT; kt++) {
        if (kt < KT - 1) asm volatile("cp.async.wait_group 1;\n");
        else             asm volatile("cp.async.wait_group 0;\n");
        __syncthreads();
        // issue next tile into stage s_nxt (== stage (kt-1)%3, whose readers all
        // finished before the barrier above)
        if (kt + 2 < KT) GISSUE(s_nxt, kt + 2);

        const uint32_t so = (uint32_t)s_cur * 32768u;
#pragma unroll
        for (int ks = 0; ks < 4; ks++) {
            int a0[4], a1[4];
            ldsm4(sbase + so + aAb + koff[ks], a0);
            ldsm4(sbase + so + aAb + 2048 + koff[ks], a1);
#pragma unroll
            for (int p = 0; p < 4; p++) {
                int bf[4];
                ldsm4(sbase + so + aBb + p * 2048 + koff[ks], bf);
                mma_bf16(acc[0][2 * p],     a0, bf[0], bf[1]);
                mma_bf16(acc[1][2 * p],     a1, bf[0], bf[1]);
                mma_bf16(acc[0][2 * p + 1], a0, bf[2], bf[3]);
                mma_bf16(acc[1][2 * p + 1], a1, bf[2], bf[3]);
            }
        }
        if (++s_cur == 3) s_cur = 0;
        if (++s_nxt == 3) s_nxt = 0;
    }
#undef GISSUE

    // epilogue
    const float sa = __fdiv_rn(amax_get(amaxA, nA), 127.0f);
    const float sb = __fdiv_rn(amax_get(amaxB, nB), 127.0f);
    const float sc = sa * sb;
    float lmax = 0.0f;
#pragma unroll
    for (int mi = 0; mi < 2; mi++) {
        const int rowb = m0 + wm * 32 + mi * 16 + gid;
#pragma unroll
        for (int nj = 0; nj < 8; nj++) {
            const int col = n0 + wn * 64 + nj * 8 + 2 * tig;
            const float bi0 = bias[col], bi1 = bias[col + 1];
#pragma unroll
            for (int half = 0; half < 2; half++) {
                const int row = rowb + half * 8;
                const size_t off = (size_t)row * N + col;
                float v0 = acc[mi][nj][half * 2]     * sc + bi0;
                float v1 = acc[mi][nj][half * 2 + 1] * sc + bi1;
                if (EPI == 1) {
                    float2 rv = *reinterpret_cast<const float2*>(&res[off]);
                    v0 += rv.x; v1 += rv.y;
                }
                if (EPI == 2) {
                    v0 = 0.5f * v0 * (1.0f + erff(v0 * 0.70710678118654752440f));
                    v1 = 0.5f * v1 * (1.0f + erff(v1 * 0.70710678118654752440f));
                    lmax = fmaxf(lmax, fmaxf(fabsf(v0), fabsf(v1)));
                }
                *reinterpret_cast<float2*>(&C[off]) = make_float2(v0, v1);
            }
        }
    }
    if (EPI == 2) {
#pragma unroll
        for (int o = 16; o > 0; o >>= 1)
            lmax = fmaxf(lmax, __shfl_xor_sync(0xffffffffu, lmax, o));
        __shared__ float sred[8];
        if (lane == 0) sred[warp] = lmax;
        __syncthreads();
        if (tid == 0) {
            float t = sred[0];
#pragma unroll
            for (int k = 1; k < 8; k++) t = fmaxf(t, sred[k]);
            atomicMaxF(gmax + ((blockIdx.y * gridDim.x + blockIdx.x) & 31) * 64, t);
        }
    }
}

// ---------------- temporal attention: one block per (b, c, h) ----------------
__global__ __launch_bounds__(256) void attn_k(const float* __restrict__ qkv,
                                              float* __restrict__ o,
                                              float* __restrict__ slot) {
    __shared__ float sQ[64][64];   // Q, later reused for V
    __shared__ float sKt[64][64];  // K transposed + rotated: [d][(t+d)&63]
    __shared__ float sS[64][64];   // scores rotated: [t][(s+t)&63]
    int id = blockIdx.x, tid = threadIdx.x;
    int h = id % 12, c = (id / 12) & 63, b = id / (12 * 64);
    size_t base = ((size_t)(b * 4096 + c * 64)) * DQKV + h * 64;

    for (int i = tid; i < 1024; i += 256) {
        int t = i >> 4, c4 = (i & 15) * 4;
        float4 q4 = *reinterpret_cast<const float4*>(&qkv[base + (size_t)t * DQKV + c4]);
        *reinterpret_cast<float4*>(&sQ[t][c4]) = q4;
        float4 k4 = *reinterpret_cast<const float4*>(&qkv[base + (size_t)t * DQKV + 768 + c4]);
        sKt[c4 + 0][(t + c4 + 0) & 63] = k4.x;
        sKt[c4 + 1][(t + c4 + 1) & 63] = k4.y;
        sKt[c4 + 2][(t + c4 + 2) & 63] = k4.z;
        sKt[c4 + 3][(t + c4 + 3) & 63] = k4.w;
    }
    __syncthreads();

    int i4 = tid >> 4, j4 = tid & 15;
    {
        // packed accumulators: acc2[i][0] = (j0, j1), acc2[i][1] = (j2, j3)
        uint64_t acc2[4][2];
        const uint64_t z = pack2(0.0f, 0.0f);
#pragma unroll
        for (int i = 0; i < 4; i++) { acc2[i][0] = z; acc2[i][1] = z; }
        // d unrolled by 4: Q read as float4 (aligned, broadcast); accumulation
        // order over d preserved exactly (dd sequential inner); per-component
        // fma.rn identical to scalar version.
#pragma unroll 2
        for (int d = 0; d < 64; d += 4) {
            float q4v[4][4];
#pragma unroll
            for (int i = 0; i < 4; i++) {
                float4 q4 = *reinterpret_cast<const float4*>(&sQ[i4 * 4 + i][d]);
                q4v[i][0] = q4.x; q4v[i][1] = q4.y; q4v[i][2] = q4.z; q4v[i][3] = q4.w;
            }
#pragma unroll
            for (int dd = 0; dd < 4; dd++) {
                int dcur = d + dd;
                float kb[4];
#pragma unroll
                for (int j = 0; j < 4; j++)
                    kb[j] = sKt[dcur][((j4 * 4 + j) + dcur) & 63];
                uint64_t kb01 = pack2(kb[0], kb[1]);
                uint64_t kb23 = pack2(kb[2], kb[3]);
#pragma unroll
                for (int i = 0; i < 4; i++) {
                    uint64_t qq = pack2(q4v[i][dd], q4v[i][dd]);
                    ffma2(acc2[i][0], qq, kb01);
                    ffma2(acc2[i][1], qq, kb23);
                }
            }
        }
#pragma unroll
        for (int i = 0; i < 4; i++) {
            int tt = i4 * 4 + i;
            float a0, a1, a2, a3;
            unpack2(acc2[i][0], a0, a1);
            unpack2(acc2[i][1], a2, a3);
            sS[tt][((j4 * 4 + 0) + tt) & 63] = a0 * 0.125f;
            sS[tt][((j4 * 4 + 1) + tt) & 63] = a1 * 0.125f;
            sS[tt][((j4 * 4 + 2) + tt) & 63] = a2 * 0.125f;
            sS[tt][((j4 * 4 + 3) + tt) & 63] = a3 * 0.125f;
        }
    }
    __syncthreads();

    for (int i = tid; i < 1024; i += 256) {
        int t = i >> 4, c4 = (i & 15) * 4;
        float4 v4 = *reinterpret_cast<const float4*>(&qkv[base + (size_t)t * DQKV + 1536 + c4]);
        *reinterpret_cast<float4*>(&sQ[t][c4]) = v4;
    }
    // parallel softmax: 4 threads per row, 16 elements each; combine via shfl
    {
        int r = tid >> 2, qq = tid & 3;
        int sbeg = qq * 16;
        float m = -3.402823466e38f;
#pragma unroll
        for (int i = 0; i < 16; i++) m = fmaxf(m, sS[r][(sbeg + i + r) & 63]);
        m = fmaxf(m, __shfl_xor_sync(0xffffffffu, m, 1));
        m = fmaxf(m, __shfl_xor_sync(0xffffffffu, m, 2));
        float sum = 0.0f;
#pragma unroll
        for (int i = 0; i < 16; i++) {
            float e = expf(sS[r][(sbeg + i + r) & 63] - m);
            sS[r][(sbeg + i + r) & 63] = e;
            sum += e;
        }
        sum += __shfl_xor_sync(0xffffffffu, sum, 1);
        sum += __shfl_xor_sync(0xffffffffu, sum, 2);
        float inv = __fdiv_rn(1.0f, sum);
#pragma unroll
        for (int i = 0; i < 16; i++) sS[r][(sbeg + i + r) & 63] *= inv;
    }
    __syncthreads();

    // O = P @ V with packed f32x2 FMAs (j pairs); per-component order identical
    uint64_t acc2[4][2];
    const uint64_t z2 = pack2(0.0f, 0.0f);
#pragma unroll
    for (int i = 0; i < 4; i++) { acc2[i][0] = z2; acc2[i][1] = z2; }
#pragma unroll 4
    for (int s = 0; s < 64; s++) {
        float4 vb4 = *reinterpret_cast<const float4*>(&sQ[s][j4 * 4]);
        uint64_t v01 = pack2(vb4.x, vb4.y);
        uint64_t v23 = pack2(vb4.z, vb4.w);
        float pa[4];
#pragma unroll
        for (int i = 0; i < 4; i++) { int tt = i4 * 4 + i; pa[i] = sS[tt][(s + tt) & 63]; }
#pragma unroll
        for (int i = 0; i < 4; i++) {
            uint64_t pp = pack2(pa[i], pa[i]);
            ffma2(acc2[i][0], pp, v01);
            ffma2(acc2[i][1], pp, v23);
        }
    }
    float lmax = 0.0f;
#pragma unroll
    for (int i = 0; i < 4; i++) {
        int tt = i4 * 4 + i;
        size_t orow = ((size_t)(b * 4096 + c * 64 + tt)) * DM + h * 64;
        float a0, a1, a2, a3;
        unpack2(acc2[i][0], a0, a1);
        unpack2(acc2[i][1], a2, a3);
        o[orow + j4 * 4 + 0] = a0;
        o[orow + j4 * 4 + 1] = a1;
        o[orow + j4 * 4 + 2] = a2;
        o[orow + j4 * 4 + 3] = a3;
        lmax = fmaxf(lmax, fmaxf(fmaxf(fabsf(a0), fabsf(a1)), fmaxf(fabsf(a2), fabsf(a3))));
    }
#pragma unroll
    for (int off = 16; off > 0; off >>= 1)
        lmax = fmaxf(lmax, __shfl_xor_sync(0xffffffffu, lmax, off));
    if ((tid & 31) == 0) atomicMaxF(slot + (blockIdx.x & 31) * 64, lmax);
}

// ---------------- launch ----------------
extern "C" void kernel_launch(void* const* d_in, const int* in_sizes, int n_in,
                              void* d_out, int out_size) {
    const float* x      = (const float*)d_in[0];
    const float* ln1_g  = (const float*)d_in[1];
    const float* ln1_b  = (const float*)d_in[2];
    const float* qkv_w  = (const float*)d_in[3];
    const float* qkv_b  = (const float*)d_in[4];
    const float* proj_w = (const float*)d_in[5];
    const float* proj_b = (const float*)d_in[6];
    const float* ln2_g  = (const float*)d_in[7];
    const float* ln2_b  = (const float*)d_in[8];
    const float* fc1_w  = (const float*)d_in[9];
    const float* fc1_b  = (const float*)d_in[10];
    const float* fc2_w  = (const float*)d_in[11];
    const float* fc2_b  = (const float*)d_in[12];

    float *pf, *pqkv, *px2, *pfc1, *pamax, *pslots;
    __nv_bfloat16 *pq, *pfc1q, *pwqkv, *pwproj, *pwfc1, *pwfc2;
    cudaGetSymbolAddress((void**)&pf,    g_f);
    cudaGetSymbolAddress((void**)&pqkv,  g_qkv);
    cudaGetSymbolAddress((void**)&px2,   g_x2);
    cudaGetSymbolAddress((void**)&pfc1,  g_fc1);
    cudaGetSymbolAddress((void**)&pq,    g_qb);
    cudaGetSymbolAddress((void**)&pfc1q, g_fc1q);
    cudaGetSymbolAddress((void**)&pwqkv, g_wqkv);
    cudaGetSymbolAddress((void**)&pwproj,g_wproj);
    cudaGetSymbolAddress((void**)&pwfc1, g_wfc1);
    cudaGetSymbolAddress((void**)&pwfc2, g_wfc2);
    cudaGetSymbolAddress((void**)&pamax, g_amax);
    cudaGetSymbolAddress((void**)&pslots,g_slots);

    const int SMEM = 3 * 32768;   // 3 stages x 32KB = 96KB
    cudaFuncSetAttribute(gemm_bf16_k<0>, cudaFuncAttributeMaxDynamicSharedMemorySize, SMEM);
    cudaFuncSetAttribute(gemm_bf16_k<1>, cudaFuncAttributeMaxDynamicSharedMemorySize, SMEM);
    cudaFuncSetAttribute(gemm_bf16_k<2>, cudaFuncAttributeMaxDynamicSharedMemorySize, SMEM);

    // fork: weight prep runs on a side stream, overlapped with ln1 + quant_a
    cudaStream_t s2;
    cudaStreamCreateWithFlags(&s2, cudaStreamNonBlocking);
    cudaEvent_t eFork, eJoin;
    cudaEventCreateWithFlags(&eFork, cudaEventDisableTiming);
    cudaEventCreateWithFlags(&eJoin, cudaEventDisableTiming);

    cudaEventRecord(eFork, 0);
    cudaStreamWaitEvent(s2, eFork, 0);
    absmax_w_k<<<dim3(512, 4), 256, 0, s2>>>(qkv_w, proj_w, fc1_w, fc2_w, pamax);
    quant_w_k<<<dim3(512, 4), 256, 0, s2>>>(qkv_w, proj_w, fc1_w, fc2_w,
                                            pwqkv, pwproj, pwfc1, pwfc2, pamax);
    cudaEventRecord(eJoin, s2);

    // attn branch (main stream, overlapped with weight prep)
    ln_k<<<NTOK, 192>>>(x, ln1_g, ln1_b, pf, pslots + 0 * 2048);
    quant_a_k<<<3072, 256>>>(pf, pq, NTOK * DM / 8, pslots + 0 * 2048);
    cudaStreamWaitEvent(0, eJoin, 0);   // join: weights ready before first GEMM
    gemm_bf16_k<0><<<dim3(DQKV / 128, NTOK / 128), 256, SMEM>>>(
        pq, pwqkv, NTOK, DQKV, DM, pslots + 0 * 2048, 32, pamax + 4, 1,
        qkv_b, nullptr, pqkv, nullptr);
    attn_k<<<8 * 64 * 12, 256>>>(pqkv, pf, pslots + 1 * 2048);
    quant_a_k<<<3072, 256>>>(pf, pq, NTOK * DM / 8, pslots + 1 * 2048);
    gemm_bf16_k<1><<<dim3(DM / 128, NTOK / 128), 256, SMEM>>>(
        pq, pwproj, NTOK, DM, DM, pslots + 1 * 2048, 32, pamax + 5, 1,
        proj_b, x, px2, nullptr);

    // mlp branch
    ln_k<<<NTOK, 192>>>(px2, ln2_g, ln2_b, pf, pslots + 2 * 2048);
    quant_a_k<<<3072, 256>>>(pf, pq, NTOK * DM / 8, pslots + 2 * 2048);
    gemm_bf16_k<2><<<dim3(DFC / 128, NTOK / 128), 256, SMEM>>>(
        pq, pwfc1, NTOK, DFC, DM, pslots + 2 * 2048, 32, pamax + 6, 1,
        fc1_b, nullptr, pfc1, pslots + 3 * 2048);
    quant_a_k<<<6144, 256>>>(pfc1, pfc1q, NTOK * DFC / 8, pslots + 3 * 2048);
    gemm_bf16_k<1><<<dim3(DM / 128, NTOK / 128), 256, SMEM>>>(
        pfc1q, pwfc2, NTOK, DM, DFC, pslots + 3 * 2048, 32, pamax + 7, 1,
        fc2_b, px2, (float*)d_out, nullptr);

    cudaStreamDestroy(s2);
    cudaEventDestroy(eFork);
    cudaEventDestroy(eJoin);
}

// round 15
// speedup vs baseline: 1.0055x; 1.0055x over previous
#include <cuda_runtime.h>
#include <cuda_bf16.h>
#include <cstdint>
#include <math.h>

#define NTOK 32768          // B * C * T = 8 * 64 * 64
#define DM   768
#define DQKV 2304
#define DFC  3072

// ---------------- scratch (device globals; no allocations) ----------------
// Device globals are zero-initialized at module load; amax slots are updated only
// via atomicMax with input-determined values, so graph replay is idempotent.
__device__ __align__(16) float  g_f[(size_t)NTOK * DM];
__device__ __align__(16) float  g_qkv[(size_t)NTOK * DQKV];
__device__ __align__(16) float  g_x2[(size_t)NTOK * DM];
__device__ __align__(16) float  g_fc1[(size_t)NTOK * DFC];
__device__ __align__(16) __nv_bfloat16 g_qb[(size_t)NTOK * DM];     // quantized act as bf16
__device__ __align__(16) __nv_bfloat16 g_fc1q[(size_t)NTOK * DFC];
__device__ __align__(16) __nv_bfloat16 g_wqkv[DQKV * DM];
__device__ __align__(16) __nv_bfloat16 g_wproj[DM * DM];
__device__ __align__(16) __nv_bfloat16 g_wfc1[DFC * DM];
__device__ __align__(16) __nv_bfloat16 g_wfc2[DM * DFC];
__device__ __align__(16) float  g_amax[16];        // 4..7 weight amax
__device__ __align__(16) float  g_slots[4 * 2048]; // spread amax slots (32 used, stride 64)

__device__ __forceinline__ void atomicMaxF(float* a, float v) {
    atomicMax(reinterpret_cast<unsigned int*>(a), __float_as_uint(v)); // v >= 0
}
__device__ __forceinline__ uint32_t smem_u32(const void* p) {
    return (uint32_t)__cvta_generic_to_shared(p);
}
__device__ __forceinline__ void cp16(uint32_t dst, const void* src) {
    asm volatile("cp.async.cg.shared.global [%0], [%1], 16;\n" :: "r"(dst), "l"(src));
}
__device__ __forceinline__ void ldsm4(uint32_t a, int* r) {
    asm volatile("ldmatrix.sync.aligned.m8n8.x4.shared.b16 {%0,%1,%2,%3}, [%4];"
                 : "=r"(r[0]), "=r"(r[1]), "=r"(r[2]), "=r"(r[3]) : "r"(a));
}
__device__ __forceinline__ void mma_bf16(float* c, const int* a, int b0, int b1) {
    asm volatile(
        "mma.sync.aligned.m16n8k16.row.col.f32.bf16.bf16.f32 "
        "{%0,%1,%2,%3}, {%4,%5,%6,%7}, {%8,%9}, {%0,%1,%2,%3};\n"
        : "+f"(c[0]), "+f"(c[1]), "+f"(c[2]), "+f"(c[3])
        : "r"(a[0]), "r"(a[1]), "r"(a[2]), "r"(a[3]), "r"(b0), "r"(b1));
}
// streaming (evict-first) float2 store for single-consumer bulk outputs
__device__ __forceinline__ void stg_cs2(float* p, float v0, float v1) {
    asm volatile("st.global.cs.v2.f32 [%0], {%1, %2};" :: "l"(p), "f"(v0), "f"(v1)
                 : "memory");
}

// max over n slot entries (stride 64 floats); n=1 for plain scalar
__device__ __forceinline__ float amax_get(const float* __restrict__ p, int n) {
    float m = p[0];
    for (int i = 1; i < n; i++) m = fmaxf(m, p[i * 64]);
    return fmaxf(m, 1e-8f);
}

// quantize two floats -> packed bf16x2 (values are small ints, conversion exact)
__device__ __forceinline__ uint32_t q2bf(float a, float b, float s) {
    float ra = fminf(fmaxf(rintf(__fdiv_rn(a, s)), -128.0f), 127.0f);
    float rb = fminf(fmaxf(rintf(__fdiv_rn(b, s)), -128.0f), 127.0f);
    uint32_t r;
    asm("cvt.rn.bf16x2.f32 %0, %1, %2;" : "=r"(r) : "f"(rb), "f"(ra)); // hi=rb, lo=ra
    return r;
}

// ---------------- weight absmax (segmented, 2x float4 per iter) ----------------
__global__ __launch_bounds__(256) void absmax_w_k(
    const float* __restrict__ w0, const float* __restrict__ w1,
    const float* __restrict__ w2, const float* __restrict__ w3, float* __restrict__ amax)
{
    const float* w; int n8;
    switch (blockIdx.y) {
        case 0: w = w0; n8 = DQKV * DM / 8; break;
        case 1: w = w1; n8 = DM * DM / 8;   break;
        case 2: w = w2; n8 = DFC * DM / 8;  break;
        default: w = w3; n8 = DM * DFC / 8; break;
    }
    float m = 0.0f;
#pragma unroll 2
    for (int i = blockIdx.x * 256 + threadIdx.x; i < n8; i += gridDim.x * 256) {
        float4 a = reinterpret_cast<const float4*>(w)[2 * i];
        float4 b = reinterpret_cast<const float4*>(w)[2 * i + 1];
        m = fmaxf(m, fmaxf(fmaxf(fabsf(a.x), fabsf(a.y)), fmaxf(fabsf(a.z), fabsf(a.w))));
        m = fmaxf(m, fmaxf(fmaxf(fabsf(b.x), fabsf(b.y)), fmaxf(fabsf(b.z), fabsf(b.w))));
    }
#pragma unroll
    for (int o = 16; o > 0; o >>= 1) m = fmaxf(m, __shfl_xor_sync(0xffffffffu, m, o));
    __shared__ float sm[8];
    if ((threadIdx.x & 31) == 0) sm[threadIdx.x >> 5] = m;
    __syncthreads();
    if (threadIdx.x == 0) {
        float t = sm[0];
#pragma unroll
        for (int k = 1; k < 8; k++) t = fmaxf(t, sm[k]);
        atomicMaxF(&amax[4 + blockIdx.y], t);
    }
}

// ---------------- weight quantize (segmented, 2x float4 -> uint4) ----------------
__global__ __launch_bounds__(256) void quant_w_k(
    const float* __restrict__ w0, const float* __restrict__ w1,
    const float* __restrict__ w2, const float* __restrict__ w3,
    __nv_bfloat16* __restrict__ q0, __nv_bfloat16* __restrict__ q1,
    __nv_bfloat16* __restrict__ q2, __nv_bfloat16* __restrict__ q3,
    const float* __restrict__ amax)
{
    const float* w; __nv_bfloat16* q; int n8;
    switch (blockIdx.y) {
        case 0: w = w0; q = q0; n8 = DQKV * DM / 8; break;
        case 1: w = w1; q = q1; n8 = DM * DM / 8;   break;
        case 2: w = w2; q = q2; n8 = DFC * DM / 8;  break;
        default: w = w3; q = q3; n8 = DM * DFC / 8; break;
    }
    float s = __fdiv_rn(amax_get(&amax[4 + blockIdx.y], 1), 127.0f);
#pragma unroll 2
    for (int i = blockIdx.x * 256 + threadIdx.x; i < n8; i += gridDim.x * 256) {
        float4 a = reinterpret_cast<const float4*>(w)[2 * i];
        float4 b = reinterpret_cast<const float4*>(w)[2 * i + 1];
        uint4 p;
        p.x = q2bf(a.x, a.y, s);
        p.y = q2bf(a.z, a.w, s);
        p.z = q2bf(b.x, b.y, s);
        p.w = q2bf(b.z, b.w, s);
        reinterpret_cast<uint4*>(q)[i] = p;
    }
}

// ---------------- activation quantize (2x float4 -> uint4, slot-reduced scale) ----
__global__ __launch_bounds__(256) void quant_a_k(const float* __restrict__ x,
                                                 __nv_bfloat16* __restrict__ q, int n8,
                                                 const float* __restrict__ slots) {
    float s = __fdiv_rn(amax_get(slots, 32), 127.0f);
#pragma unroll 4
    for (int i = blockIdx.x * 256 + threadIdx.x; i < n8; i += gridDim.x * 256) {
        float4 a = reinterpret_cast<const float4*>(x)[2 * i];
        float4 b = reinterpret_cast<const float4*>(x)[2 * i + 1];
        uint4 p;
        p.x = q2bf(a.x, a.y, s);
        p.y = q2bf(a.z, a.w, s);
        p.z = q2bf(b.x, b.y, s);
        p.w = q2bf(b.z, b.w, s);
        reinterpret_cast<uint4*>(q)[i] = p;
    }
}

// ---------------- layernorm + fused absmax (192 threads, float4) ----------------
__global__ __launch_bounds__(192) void ln_k(const float* __restrict__ x,
                                            const float* __restrict__ g,
                                            const float* __restrict__ b,
                                            float* __restrict__ out,
                                            float* __restrict__ slot) {
    __shared__ float sm[6];
    __shared__ float bc[2];
    int row = blockIdx.x, tid = threadIdx.x;
    int lane = tid & 31, wid = tid >> 5;   // 6 warps
    float4 v = reinterpret_cast<const float4*>(x + (size_t)row * DM)[tid];

    float s = v.x + v.y + v.z + v.w;
#pragma unroll
    for (int o = 16; o > 0; o >>= 1) s += __shfl_xor_sync(0xffffffffu, s, o);
    if (lane == 0) sm[wid] = s;
    __syncthreads();
    if (wid == 0) {
        float t = (lane < 6) ? sm[lane] : 0.0f;
#pragma unroll
        for (int o = 4; o > 0; o >>= 1) t += __shfl_xor_sync(0xffffffffu, t, o);
        if (lane == 0) bc[0] = t * (1.0f / 768.0f);
    }
    __syncthreads();
    float mean = bc[0];
    float4 d = make_float4(v.x - mean, v.y - mean, v.z - mean, v.w - mean);
    float ss = d.x * d.x + d.y * d.y + d.z * d.z + d.w * d.w;
#pragma unroll
    for (int o = 16; o > 0; o >>= 1) ss += __shfl_xor_sync(0xffffffffu, ss, o);
    if (lane == 0) sm[wid] = ss;
    __syncthreads();
    if (wid == 0) {
        float t = (lane < 6) ? sm[lane] : 0.0f;
#pragma unroll
        for (int o = 4; o > 0; o >>= 1) t += __shfl_xor_sync(0xffffffffu, t, o);
        if (lane == 0) bc[1] = __frsqrt_rn(t * (1.0f / 768.0f) + 1e-5f);
    }
    __syncthreads();
    float rs = bc[1];
    float4 gg = reinterpret_cast<const float4*>(g)[tid];
    float4 bb = reinterpret_cast<const float4*>(b)[tid];
    float4 o4;
    o4.x = d.x * rs * gg.x + bb.x;
    o4.y = d.y * rs * gg.y + bb.y;
    o4.z = d.z * rs * gg.z + bb.z;
    o4.w = d.w * rs * gg.w + bb.w;
    reinterpret_cast<float4*>(out + (size_t)row * DM)[tid] = o4;

    float lm = fmaxf(fmaxf(fabsf(o4.x), fabsf(o4.y)), fmaxf(fabsf(o4.z), fabsf(o4.w)));
#pragma unroll
    for (int o = 16; o > 0; o >>= 1) lm = fmaxf(lm, __shfl_xor_sync(0xffffffffu, lm, o));
    if (lane == 0) sm[wid] = lm;
    __syncthreads();
    if (tid == 0) {
        float t = sm[0];
#pragma unroll
        for (int k = 1; k < 6; k++) t = fmaxf(t, sm[k]);
        atomicMaxF(slot + (row & 31) * 64, t);
    }
}

// ---------------- bf16 HMMA GEMM, C = A[M,K] * B[N,K]^T ----------------
// Block 128x128, BK=64 (128B rows, XOR swizzle on 16B chunks), 3-stage cp.async
// with a single __syncthreads per k-iteration. Warp grid 4(M) x 2(N); warp tile
// 32x64 via mma.m16n8k16.bf16 (fp32 accum).
// EPI: 0 = bias (streaming C), 1 = bias + residual,
//      2 = bias + exact GELU + fused absmax (streaming C)
template<int EPI>
__global__ __launch_bounds__(256, 2) void gemm_bf16_k(
    const __nv_bfloat16* __restrict__ A, const __nv_bfloat16* __restrict__ B,
    int M, int N, int K,
    const float* __restrict__ amaxA, int nA,
    const float* __restrict__ amaxB, int nB,
    const float* __restrict__ bias, const float* __restrict__ res,
    float* __restrict__ C, float* __restrict__ gmax)
{
    extern __shared__ __align__(1024) char smem[];   // 3 stages x (A 16KB + B 16KB)
    const uint32_t sbase = smem_u32(smem);
    const int tid  = threadIdx.x;
    const int lane = tid & 31, warp = tid >> 5;
    const int wm = warp & 3, wn = warp >> 2;
    const int m0 = blockIdx.y * 128, n0 = blockIdx.x * 128;
    const int gid = lane >> 2, tig = lane & 3;

    float acc[2][8][4];
#pragma unroll
    for (int mi = 0; mi < 2; mi++)
#pragma unroll
        for (int nj = 0; nj < 8; nj++)
#pragma unroll
            for (int r = 0; r < 4; r++) acc[mi][nj][r] = 0.0f;

    // global->smem mapping: thread t handles row t>>1, chunks (t&1)*4 .. +3 (16B each)
    const int lrow = tid >> 1, lcb = (tid & 1) * 4;
    const char* gA = (const char*)(A + (size_t)(m0 + lrow) * K) + lcb * 16;
    const char* gB = (const char*)(B + (size_t)(n0 + lrow) * K) + lcb * 16;
    uint32_t dst[4];
#pragma unroll
    for (int c = 0; c < 4; c++)
        dst[c] = lrow * 128 + (((lcb + c) ^ (lrow & 7)) << 4);

    // ldmatrix lane addressing (row-dependent swizzle s = row & 7 = lane & 7)
    const int s7 = lane & 7;
    uint32_t koff[4];
#pragma unroll
    for (int ks = 0; ks < 4; ks++) koff[ks] = ((ks * 2) ^ (s7 & 6)) << 4;
    const int rowA0 = wm * 32 + s7 + ((lane >> 3) & 1) * 8;
    const uint32_t aAb = rowA0 * 128 + (((((lane >> 4) & 1)) ^ (s7 & 1)) << 4);
    const int rowB0 = wn * 64 + s7 + ((lane >> 4) & 1) * 8;
    const uint32_t aBb = 16384 + rowB0 * 128 + (((((lane >> 3) & 1)) ^ (s7 & 1)) << 4);

    const int KT = K >> 6;   // >= 12 always

#define GISSUE(stg, ktile) do {                                          \
        const uint32_t so_ = (uint32_t)(stg) * 32768u;                   \
        const char* pA_ = gA + (size_t)(ktile) * 128;                    \
        const char* pB_ = gB + (size_t)(ktile) * 128;                    \
        _Pragma("unroll")                                                \
        for (int c_ = 0; c_ < 4; c_++) {                                 \
            cp16(sbase + so_ + dst[c_], pA_ + c_ * 16);                  \
            cp16(sbase + so_ + 16384 + dst[c_], pB_ + c_ * 16);          \
        }                                                                \
        asm volatile("cp.async.commit_group;\n");                        \
    } while (0)

    // prologue: stages 0 and 1 (groups 0, 1)
    GISSUE(0, 0);
    GISSUE(1, 1);

    int s_cur = 0, s_nxt = 2;
    for (int kt = 0; kt < KT; kt++) {
        if (kt < KT - 1) asm volatile("cp.async.wait_group 1;\n");
        else             asm volatile("cp.async.wait_group 0;\n");
        __syncthreads();
        // issue next tile into stage s_nxt (== stage (kt-1)%3, whose readers all
        // finished before the barrier above)
        if (kt + 2 < KT) GISSUE(s_nxt, kt + 2);

        const uint32_t so = (uint32_t)s_cur * 32768u;
#pragma unroll
        for (int ks = 0; ks < 4; ks++) {
            int a0[4], a1[4];
            ldsm4(sbase + so + aAb + koff[ks], a0);
            ldsm4(sbase + so + aAb + 2048 + koff[ks], a1);
#pragma unroll
            for (int p = 0; p < 4; p++) {
                int bf[4];
                ldsm4(sbase + so + aBb + p * 2048 + koff[ks], bf);
                mma_bf16(acc[0][2 * p],     a0, bf[0], bf[1]);
                mma_bf16(acc[1][2 * p],     a1, bf[0], bf[1]);
                mma_bf16(acc[0][2 * p + 1], a0, bf[2], bf[3]);
                mma_bf16(acc[1][2 * p + 1], a1, bf[2], bf[3]);
            }
        }
        if (++s_cur == 3) s_cur = 0;
        if (++s_nxt == 3) s_nxt = 0;
    }
#undef GISSUE

    // epilogue
    const float sa = __fdiv_rn(amax_get(amaxA, nA), 127.0f);
    const float sb = __fdiv_rn(amax_get(amaxB, nB), 127.0f);
    const float sc = sa * sb;
    float lmax = 0.0f;
#pragma unroll
    for (int mi = 0; mi < 2; mi++) {
        const int rowb = m0 + wm * 32 + mi * 16 + gid;
#pragma unroll
        for (int nj = 0; nj < 8; nj++) {
            const int col = n0 + wn * 64 + nj * 8 + 2 * tig;
            const float bi0 = bias[col], bi1 = bias[col + 1];
#pragma unroll
            for (int half = 0; half < 2; half++) {
                const int row = rowb + half * 8;
                const size_t off = (size_t)row * N + col;
                float v0 = acc[mi][nj][half * 2]     * sc + bi0;
                float v1 = acc[mi][nj][half * 2 + 1] * sc + bi1;
                if (EPI == 1) {
                    float2 rv = *reinterpret_cast<const float2*>(&res[off]);
                    v0 += rv.x; v1 += rv.y;
                }
                if (EPI == 2) {
                    v0 = 0.5f * v0 * (1.0f + erff(v0 * 0.70710678118654752440f));
                    v1 = 0.5f * v1 * (1.0f + erff(v1 * 0.70710678118654752440f));
                    lmax = fmaxf(lmax, fmaxf(fabsf(v0), fabsf(v1)));
                }
                if (EPI == 1) {
                    *reinterpret_cast<float2*>(&C[off]) = make_float2(v0, v1);
                } else {
                    // single-consumer bulk output: evict-first streaming store
                    stg_cs2(&C[off], v0, v1);
                }
            }
        }
    }
    if (EPI == 2) {
#pragma unroll
        for (int o = 16; o > 0; o >>= 1)
            lmax = fmaxf(lmax, __shfl_xor_sync(0xffffffffu, lmax, o));
        __shared__ float sred[8];
        if (lane == 0) sred[warp] = lmax;
        __syncthreads();
        if (tid == 0) {
            float t = sred[0];
#pragma unroll
            for (int k = 1; k < 8; k++) t = fmaxf(t, sred[k]);
            atomicMaxF(gmax + ((blockIdx.y * gridDim.x + blockIdx.x) & 31) * 64, t);
        }
    }
}

// ---------------- temporal attention: one block per (b, c, h) ----------------
__global__ __launch_bounds__(256) void attn_k(const float* __restrict__ qkv,
                                              float* __restrict__ o,
                                              float* __restrict__ slot) {
    __shared__ float sQ[64][64];   // Q, later reused for V
    __shared__ float sKt[64][64];  // K transposed + rotated: [d][(t+d)&63]
    __shared__ float sS[64][64];   // scores rotated: [t][(s+t)&63]
    int id = blockIdx.x, tid = threadIdx.x;
    int h = id % 12, c = (id / 12) & 63, b = id / (12 * 64);
    size_t base = ((size_t)(b * 4096 + c * 64)) * DQKV + h * 64;

    for (int i = tid; i < 1024; i += 256) {
        int t = i >> 4, c4 = (i & 15) * 4;
        float4 q4 = *reinterpret_cast<const float4*>(&qkv[base + (size_t)t * DQKV + c4]);
        *reinterpret_cast<float4*>(&sQ[t][c4]) = q4;
        float4 k4 = *reinterpret_cast<const float4*>(&qkv[base + (size_t)t * DQKV + 768 + c4]);
        sKt[c4 + 0][(t + c4 + 0) & 63] = k4.x;
        sKt[c4 + 1][(t + c4 + 1) & 63] = k4.y;
        sKt[c4 + 2][(t + c4 + 2) & 63] = k4.z;
        sKt[c4 + 3][(t + c4 + 3) & 63] = k4.w;
    }
    __syncthreads();

    int i4 = tid >> 4, j4 = tid & 15;
    {
        float acc[4][4];
#pragma unroll
        for (int i = 0; i < 4; i++)
#pragma unroll
            for (int j = 0; j < 4; j++) acc[i][j] = 0.0f;
#pragma unroll 4
        for (int d = 0; d < 64; d++) {
            float qa[4], kb[4];
#pragma unroll
            for (int i = 0; i < 4; i++) qa[i] = sQ[i4 * 4 + i][d];
#pragma unroll
            for (int j = 0; j < 4; j++) kb[j] = sKt[d][((j4 * 4 + j) + d) & 63];
#pragma unroll
            for (int i = 0; i < 4; i++)
#pragma unroll
                for (int j = 0; j < 4; j++) acc[i][j] = fmaf(qa[i], kb[j], acc[i][j]);
        }
#pragma unroll
        for (int i = 0; i < 4; i++) {
            int tt = i4 * 4 + i;
#pragma unroll
            for (int j = 0; j < 4; j++) {
                int ss = j4 * 4 + j;
                sS[tt][(ss + tt) & 63] = acc[i][j] * 0.125f;
            }
        }
    }
    __syncthreads();

    for (int i = tid; i < 1024; i += 256) {
        int t = i >> 4, c4 = (i & 15) * 4;
        float4 v4 = *reinterpret_cast<const float4*>(&qkv[base + (size_t)t * DQKV + 1536 + c4]);
        *reinterpret_cast<float4*>(&sQ[t][c4]) = v4;
    }
    // parallel softmax: 4 threads per row, 16 elements each; combine via shfl
    {
        int r = tid >> 2, qq = tid & 3;
        int sbeg = qq * 16;
        float m = -3.402823466e38f;
#pragma unroll
        for (int i = 0; i < 16; i++) m = fmaxf(m, sS[r][(sbeg + i + r) & 63]);
        m = fmaxf(m, __shfl_xor_sync(0xffffffffu, m, 1));
        m = fmaxf(m, __shfl_xor_sync(0xffffffffu, m, 2));
        float sum = 0.0f;
#pragma unroll
        for (int i = 0; i < 16; i++) {
            float e = expf(sS[r][(sbeg + i + r) & 63] - m);
            sS[r][(sbeg + i + r) & 63] = e;
            sum += e;
        }
        sum += __shfl_xor_sync(0xffffffffu, sum, 1);
        sum += __shfl_xor_sync(0xffffffffu, sum, 2);
        float inv = __fdiv_rn(1.0f, sum);
#pragma unroll
        for (int i = 0; i < 16; i++) sS[r][(sbeg + i + r) & 63] *= inv;
    }
    __syncthreads();

    float acc[4][4];
#pragma unroll
    for (int i = 0; i < 4; i++)
#pragma unroll
        for (int j = 0; j < 4; j++) acc[i][j] = 0.0f;
#pragma unroll 4
    for (int s = 0; s < 64; s++) {
        float pa[4], vb[4];
#pragma unroll
        for (int i = 0; i < 4; i++) { int tt = i4 * 4 + i; pa[i] = sS[tt][(s + tt) & 63]; }
#pragma unroll
        for (int j = 0; j < 4; j++) vb[j] = sQ[s][j4 * 4 + j];
#pragma unroll
        for (int i = 0; i < 4; i++)
#pragma unroll
            for (int j = 0; j < 4; j++) acc[i][j] = fmaf(pa[i], vb[j], acc[i][j]);
    }
    float lmax = 0.0f;
#pragma unroll
    for (int i = 0; i < 4; i++) {
        int tt = i4 * 4 + i;
        size_t orow = ((size_t)(b * 4096 + c * 64 + tt)) * DM + h * 64;
#pragma unroll
        for (int j = 0; j < 4; j++) {
            int dd = j4 * 4 + j;
            o[orow + dd] = acc[i][j];
            lmax = fmaxf(lmax, fabsf(acc[i][j]));
        }
    }
#pragma unroll
    for (int off = 16; off > 0; off >>= 1)
        lmax = fmaxf(lmax, __shfl_xor_sync(0xffffffffu, lmax, off));
    if ((tid & 31) == 0) atomicMaxF(slot + (blockIdx.x & 31) * 64, lmax);
}

// ---------------- launch ----------------
extern "C" void kernel_launch(void* const* d_in, const int* in_sizes, int n_in,
                              void* d_out, int out_size) {
    const float* x      = (const float*)d_in[0];
    const float* ln1_g  = (const float*)d_in[1];
    const float* ln1_b  = (const float*)d_in[2];
    const float* qkv_w  = (const float*)d_in[3];
    const float* qkv_b  = (const float*)d_in[4];
    const float* proj_w = (const float*)d_in[5];
    const float* proj_b = (const float*)d_in[6];
    const float* ln2_g  = (const float*)d_in[7];
    const float* ln2_b  = (const float*)d_in[8];
    const float* fc1_w  = (const float*)d_in[9];
    const float* fc1_b  = (const float*)d_in[10];
    const float* fc2_w  = (const float*)d_in[11];
    const float* fc2_b  = (const float*)d_in[12];

    float *pf, *pqkv, *px2, *pfc1, *pamax, *pslots;
    __nv_bfloat16 *pq, *pfc1q, *pwqkv, *pwproj, *pwfc1, *pwfc2;
    cudaGetSymbolAddress((void**)&pf,    g_f);
    cudaGetSymbolAddress((void**)&pqkv,  g_qkv);
    cudaGetSymbolAddress((void**)&px2,   g_x2);
    cudaGetSymbolAddress((void**)&pfc1,  g_fc1);
    cudaGetSymbolAddress((void**)&pq,    g_qb);
    cudaGetSymbolAddress((void**)&pfc1q, g_fc1q);
    cudaGetSymbolAddress((void**)&pwqkv, g_wqkv);
    cudaGetSymbolAddress((void**)&pwproj,g_wproj);
    cudaGetSymbolAddress((void**)&pwfc1, g_wfc1);
    cudaGetSymbolAddress((void**)&pwfc2, g_wfc2);
    cudaGetSymbolAddress((void**)&pamax, g_amax);
    cudaGetSymbolAddress((void**)&pslots,g_slots);

    const int SMEM = 3 * 32768;   // 3 stages x 32KB = 96KB
    cudaFuncSetAttribute(gemm_bf16_k<0>, cudaFuncAttributeMaxDynamicSharedMemorySize, SMEM);
    cudaFuncSetAttribute(gemm_bf16_k<1>, cudaFuncAttributeMaxDynamicSharedMemorySize, SMEM);
    cudaFuncSetAttribute(gemm_bf16_k<2>, cudaFuncAttributeMaxDynamicSharedMemorySize, SMEM);

    // fork: weight prep runs on a side stream, overlapped with ln1 + quant_a
    cudaStream_t s2;
    cudaStreamCreateWithFlags(&s2, cudaStreamNonBlocking);
    cudaEvent_t eFork, eJoin;
    cudaEventCreateWithFlags(&eFork, cudaEventDisableTiming);
    cudaEventCreateWithFlags(&eJoin, cudaEventDisableTiming);

    cudaEventRecord(eFork, 0);
    cudaStreamWaitEvent(s2, eFork, 0);
    absmax_w_k<<<dim3(512, 4), 256, 0, s2>>>(qkv_w, proj_w, fc1_w, fc2_w, pamax);
    quant_w_k<<<dim3(512, 4), 256, 0, s2>>>(qkv_w, proj_w, fc1_w, fc2_w,
                                            pwqkv, pwproj, pwfc1, pwfc2, pamax);
    cudaEventRecord(eJoin, s2);

    // attn branch (main stream, overlapped with weight prep)
    ln_k<<<NTOK, 192>>>(x, ln1_g, ln1_b, pf, pslots + 0 * 2048);
    quant_a_k<<<2368, 256>>>(pf, pq, NTOK * DM / 8, pslots + 0 * 2048);
    cudaStreamWaitEvent(0, eJoin, 0);   // join: weights ready before first GEMM
    gemm_bf16_k<0><<<dim3(DQKV / 128, NTOK / 128), 256, SMEM>>>(
        pq, pwqkv, NTOK, DQKV, DM, pslots + 0 * 2048, 32, pamax + 4, 1,
        qkv_b, nullptr, pqkv, nullptr);
    attn_k<<<8 * 64 * 12, 256>>>(pqkv, pf, pslots + 1 * 2048);
    quant_a_k<<<2368, 256>>>(pf, pq, NTOK * DM / 8, pslots + 1 * 2048);
    gemm_bf16_k<1><<<dim3(DM / 128, NTOK / 128), 256, SMEM>>>(
        pq, pwproj, NTOK, DM, DM, pslots + 1 * 2048, 32, pamax + 5, 1,
        proj_b, x, px2, nullptr);

    // mlp branch
    ln_k<<<NTOK, 192>>>(px2, ln2_g, ln2_b, pf, pslots + 2 * 2048);
    quant_a_k<<<2368, 256>>>(pf, pq, NTOK * DM / 8, pslots + 2 * 2048);
    gemm_bf16_k<2><<<dim3(DFC / 128, NTOK / 128), 256, SMEM>>>(
        pq, pwfc1, NTOK, DFC, DM, pslots + 2 * 2048, 32, pamax + 6, 1,
        fc1_b, nullptr, pfc1, pslots + 3 * 2048);
    quant_a_k<<<4736, 256>>>(pfc1, pfc1q, NTOK * DFC / 8, pslots + 3 * 2048);
    gemm_bf16_k<1><<<dim3(DM / 128, NTOK / 128), 256, SMEM>>>(
        pfc1q, pwfc2, NTOK, DM, DFC, pslots + 3 * 2048, 32, pamax + 7, 1,
        fc2_b, px2, (float*)d_out, nullptr);

    cudaStreamDestroy(s2);
    cudaEventDestroy(eFork);
    cudaEventDestroy(eJoin);
}

// round 16
// speedup vs baseline: 1.0085x; 1.0030x over previous
#include <cuda_runtime.h>
#include <cuda_bf16.h>
#include <cstdint>
#include <math.h>

#define NTOK 32768          // B * C * T = 8 * 64 * 64
#define DM   768
#define DQKV 2304
#define DFC  3072

// ---------------- scratch (device globals; no allocations) ----------------
// Device globals are zero-initialized at module load; amax slots are updated only
// via atomicMax with input-determined values, so graph replay is idempotent.
__device__ __align__(16) float  g_f[(size_t)NTOK * DM];
__device__ __align__(16) float  g_qkv[(size_t)NTOK * DQKV];
__device__ __align__(16) float  g_x2[(size_t)NTOK * DM];
__device__ __align__(16) float  g_fc1[(size_t)NTOK * DFC];
__device__ __align__(16) __nv_bfloat16 g_qb[(size_t)NTOK * DM];     // quantized act as bf16
__device__ __align__(16) __nv_bfloat16 g_fc1q[(size_t)NTOK * DFC];
__device__ __align__(16) __nv_bfloat16 g_wqkv[DQKV * DM];
__device__ __align__(16) __nv_bfloat16 g_wproj[DM * DM];
__device__ __align__(16) __nv_bfloat16 g_wfc1[DFC * DM];
__device__ __align__(16) __nv_bfloat16 g_wfc2[DM * DFC];
__device__ __align__(16) float  g_amax[16];        // 4..7 weight amax
__device__ __align__(16) float  g_slots[4 * 2048]; // spread amax slots (32 used, stride 64)

__device__ __forceinline__ void atomicMaxF(float* a, float v) {
    atomicMax(reinterpret_cast<unsigned int*>(a), __float_as_uint(v)); // v >= 0
}
__device__ __forceinline__ uint32_t smem_u32(const void* p) {
    return (uint32_t)__cvta_generic_to_shared(p);
}
__device__ __forceinline__ void cp16(uint32_t dst, const void* src) {
    asm volatile("cp.async.cg.shared.global [%0], [%1], 16;\n" :: "r"(dst), "l"(src));
}
__device__ __forceinline__ void ldsm4(uint32_t a, int* r) {
    asm volatile("ldmatrix.sync.aligned.m8n8.x4.shared.b16 {%0,%1,%2,%3}, [%4];"
                 : "=r"(r[0]), "=r"(r[1]), "=r"(r[2]), "=r"(r[3]) : "r"(a));
}
__device__ __forceinline__ void mma_bf16(float* c, const int* a, int b0, int b1) {
    asm volatile(
        "mma.sync.aligned.m16n8k16.row.col.f32.bf16.bf16.f32 "
        "{%0,%1,%2,%3}, {%4,%5,%6,%7}, {%8,%9}, {%0,%1,%2,%3};\n"
        : "+f"(c[0]), "+f"(c[1]), "+f"(c[2]), "+f"(c[3])
        : "r"(a[0]), "r"(a[1]), "r"(a[2]), "r"(a[3]), "r"(b0), "r"(b1));
}
// streaming (evict-first) float2 store for single-consumer bulk outputs
__device__ __forceinline__ void stg_cs2(float* p, float v0, float v1) {
    asm volatile("st.global.cs.v2.f32 [%0], {%1, %2};" :: "l"(p), "f"(v0), "f"(v1)
                 : "memory");
}
// streaming (evict-first) float4 load for single-consumer bulk inputs
__device__ __forceinline__ float4 ldg_cs4(const float* p) {
    float4 v;
    asm volatile("ld.global.cs.v4.f32 {%0,%1,%2,%3}, [%4];"
                 : "=f"(v.x), "=f"(v.y), "=f"(v.z), "=f"(v.w) : "l"(p));
    return v;
}

// max over n slot entries (stride 64 floats); n=1 for plain scalar
__device__ __forceinline__ float amax_get(const float* __restrict__ p, int n) {
    float m = p[0];
    for (int i = 1; i < n; i++) m = fmaxf(m, p[i * 64]);
    return fmaxf(m, 1e-8f);
}

// quantize two floats -> packed bf16x2 (values are small ints, conversion exact)
__device__ __forceinline__ uint32_t q2bf(float a, float b, float s) {
    float ra = fminf(fmaxf(rintf(__fdiv_rn(a, s)), -128.0f), 127.0f);
    float rb = fminf(fmaxf(rintf(__fdiv_rn(b, s)), -128.0f), 127.0f);
    uint32_t r;
    asm("cvt.rn.bf16x2.f32 %0, %1, %2;" : "=r"(r) : "f"(rb), "f"(ra)); // hi=rb, lo=ra
    return r;
}

// ---------------- weight absmax (segmented, 2x float4 per iter) ----------------
__global__ __launch_bounds__(256) void absmax_w_k(
    const float* __restrict__ w0, const float* __restrict__ w1,
    const float* __restrict__ w2, const float* __restrict__ w3, float* __restrict__ amax)
{
    const float* w; int n8;
    switch (blockIdx.y) {
        case 0: w = w0; n8 = DQKV * DM / 8; break;
        case 1: w = w1; n8 = DM * DM / 8;   break;
        case 2: w = w2; n8 = DFC * DM / 8;  break;
        default: w = w3; n8 = DM * DFC / 8; break;
    }
    float m = 0.0f;
#pragma unroll 2
    for (int i = blockIdx.x * 256 + threadIdx.x; i < n8; i += gridDim.x * 256) {
        float4 a = reinterpret_cast<const float4*>(w)[2 * i];
        float4 b = reinterpret_cast<const float4*>(w)[2 * i + 1];
        m = fmaxf(m, fmaxf(fmaxf(fabsf(a.x), fabsf(a.y)), fmaxf(fabsf(a.z), fabsf(a.w))));
        m = fmaxf(m, fmaxf(fmaxf(fabsf(b.x), fabsf(b.y)), fmaxf(fabsf(b.z), fabsf(b.w))));
    }
#pragma unroll
    for (int o = 16; o > 0; o >>= 1) m = fmaxf(m, __shfl_xor_sync(0xffffffffu, m, o));
    __shared__ float sm[8];
    if ((threadIdx.x & 31) == 0) sm[threadIdx.x >> 5] = m;
    __syncthreads();
    if (threadIdx.x == 0) {
        float t = sm[0];
#pragma unroll
        for (int k = 1; k < 8; k++) t = fmaxf(t, sm[k]);
        atomicMaxF(&amax[4 + blockIdx.y], t);
    }
}

// ---------------- weight quantize (segmented, 2x float4 -> uint4) ----------------
__global__ __launch_bounds__(256) void quant_w_k(
    const float* __restrict__ w0, const float* __restrict__ w1,
    const float* __restrict__ w2, const float* __restrict__ w3,
    __nv_bfloat16* __restrict__ q0, __nv_bfloat16* __restrict__ q1,
    __nv_bfloat16* __restrict__ q2, __nv_bfloat16* __restrict__ q3,
    const float* __restrict__ amax)
{
    const float* w; __nv_bfloat16* q; int n8;
    switch (blockIdx.y) {
        case 0: w = w0; q = q0; n8 = DQKV * DM / 8; break;
        case 1: w = w1; q = q1; n8 = DM * DM / 8;   break;
        case 2: w = w2; q = q2; n8 = DFC * DM / 8;  break;
        default: w = w3; q = q3; n8 = DM * DFC / 8; break;
    }
    float s = __fdiv_rn(amax_get(&amax[4 + blockIdx.y], 1), 127.0f);
#pragma unroll 2
    for (int i = blockIdx.x * 256 + threadIdx.x; i < n8; i += gridDim.x * 256) {
        float4 a = reinterpret_cast<const float4*>(w)[2 * i];
        float4 b = reinterpret_cast<const float4*>(w)[2 * i + 1];
        uint4 p;
        p.x = q2bf(a.x, a.y, s);
        p.y = q2bf(a.z, a.w, s);
        p.z = q2bf(b.x, b.y, s);
        p.w = q2bf(b.z, b.w, s);
        reinterpret_cast<uint4*>(q)[i] = p;
    }
}

// ---------------- activation quantize (2x float4 -> uint4, slot-reduced scale) ----
// Input is a single-consumer bulk stream -> evict-first loads.
__global__ __launch_bounds__(256) void quant_a_k(const float* __restrict__ x,
                                                 __nv_bfloat16* __restrict__ q, int n8,
                                                 const float* __restrict__ slots) {
    float s = __fdiv_rn(amax_get(slots, 32), 127.0f);
#pragma unroll 4
    for (int i = blockIdx.x * 256 + threadIdx.x; i < n8; i += gridDim.x * 256) {
        float4 a = ldg_cs4(x + (size_t)i * 8);
        float4 b = ldg_cs4(x + (size_t)i * 8 + 4);
        uint4 p;
        p.x = q2bf(a.x, a.y, s);
        p.y = q2bf(a.z, a.w, s);
        p.z = q2bf(b.x, b.y, s);
        p.w = q2bf(b.z, b.w, s);
        reinterpret_cast<uint4*>(q)[i] = p;
    }
}

// ---------------- layernorm + fused absmax (192 threads, float4) ----------------
__global__ __launch_bounds__(192) void ln_k(const float* __restrict__ x,
                                            const float* __restrict__ g,
                                            const float* __restrict__ b,
                                            float* __restrict__ out,
                                            float* __restrict__ slot) {
    __shared__ float sm[6];
    __shared__ float bc[2];
    int row = blockIdx.x, tid = threadIdx.x;
    int lane = tid & 31, wid = tid >> 5;   // 6 warps
    float4 v = reinterpret_cast<const float4*>(x + (size_t)row * DM)[tid];

    float s = v.x + v.y + v.z + v.w;
#pragma unroll
    for (int o = 16; o > 0; o >>= 1) s += __shfl_xor_sync(0xffffffffu, s, o);
    if (lane == 0) sm[wid] = s;
    __syncthreads();
    if (wid == 0) {
        float t = (lane < 6) ? sm[lane] : 0.0f;
#pragma unroll
        for (int o = 4; o > 0; o >>= 1) t += __shfl_xor_sync(0xffffffffu, t, o);
        if (lane == 0) bc[0] = t * (1.0f / 768.0f);
    }
    __syncthreads();
    float mean = bc[0];
    float4 d = make_float4(v.x - mean, v.y - mean, v.z - mean, v.w - mean);
    float ss = d.x * d.x + d.y * d.y + d.z * d.z + d.w * d.w;
#pragma unroll
    for (int o = 16; o > 0; o >>= 1) ss += __shfl_xor_sync(0xffffffffu, ss, o);
    if (lane == 0) sm[wid] = ss;
    __syncthreads();
    if (wid == 0) {
        float t = (lane < 6) ? sm[lane] : 0.0f;
#pragma unroll
        for (int o = 4; o > 0; o >>= 1) t += __shfl_xor_sync(0xffffffffu, t, o);
        if (lane == 0) bc[1] = __frsqrt_rn(t * (1.0f / 768.0f) + 1e-5f);
    }
    __syncthreads();
    float rs = bc[1];
    float4 gg = reinterpret_cast<const float4*>(g)[tid];
    float4 bb = reinterpret_cast<const float4*>(b)[tid];
    float4 o4;
    o4.x = d.x * rs * gg.x + bb.x;
    o4.y = d.y * rs * gg.y + bb.y;
    o4.z = d.z * rs * gg.z + bb.z;
    o4.w = d.w * rs * gg.w + bb.w;
    reinterpret_cast<float4*>(out + (size_t)row * DM)[tid] = o4;

    float lm = fmaxf(fmaxf(fabsf(o4.x), fabsf(o4.y)), fmaxf(fabsf(o4.z), fabsf(o4.w)));
#pragma unroll
    for (int o = 16; o > 0; o >>= 1) lm = fmaxf(lm, __shfl_xor_sync(0xffffffffu, lm, o));
    if (lane == 0) sm[wid] = lm;
    __syncthreads();
    if (tid == 0) {
        float t = sm[0];
#pragma unroll
        for (int k = 1; k < 6; k++) t = fmaxf(t, sm[k]);
        atomicMaxF(slot + (row & 31) * 64, t);
    }
}

// ---------------- bf16 HMMA GEMM, C = A[M,K] * B[N,K]^T ----------------
// Block 128x128, BK=64 (128B rows, XOR swizzle on 16B chunks), 3-stage cp.async
// with a single __syncthreads per k-iteration. Warp grid 4(M) x 2(N); warp tile
// 32x64 via mma.m16n8k16.bf16 (fp32 accum).
// EPI: 0 = bias (streaming C), 1 = bias + residual,
//      2 = bias + exact GELU + fused absmax (streaming C)
template<int EPI>
__global__ __launch_bounds__(256, 2) void gemm_bf16_k(
    const __nv_bfloat16* __restrict__ A, const __nv_bfloat16* __restrict__ B,
    int M, int N, int K,
    const float* __restrict__ amaxA, int nA,
    const float* __restrict__ amaxB, int nB,
    const float* __restrict__ bias, const float* __restrict__ res,
    float* __restrict__ C, float* __restrict__ gmax)
{
    extern __shared__ __align__(1024) char smem[];   // 3 stages x (A 16KB + B 16KB)
    const uint32_t sbase = smem_u32(smem);
    const int tid  = threadIdx.x;
    const int lane = tid & 31, warp = tid >> 5;
    const int wm = warp & 3, wn = warp >> 2;
    const int m0 = blockIdx.y * 128, n0 = blockIdx.x * 128;
    const int gid = lane >> 2, tig = lane & 3;

    float acc[2][8][4];
#pragma unroll
    for (int mi = 0; mi < 2; mi++)
#pragma unroll
        for (int nj = 0; nj < 8; nj++)
#pragma unroll
            for (int r = 0; r < 4; r++) acc[mi][nj][r] = 0.0f;

    // global->smem mapping: thread t handles row t>>1, chunks (t&1)*4 .. +3 (16B each)
    const int lrow = tid >> 1, lcb = (tid & 1) * 4;
    const char* gA = (const char*)(A + (size_t)(m0 + lrow) * K) + lcb * 16;
    const char* gB = (const char*)(B + (size_t)(n0 + lrow) * K) + lcb * 16;
    uint32_t dst[4];
#pragma unroll
    for (int c = 0; c < 4; c++)
        dst[c] = lrow * 128 + (((lcb + c) ^ (lrow & 7)) << 4);

    // ldmatrix lane addressing (row-dependent swizzle s = row & 7 = lane & 7)
    const int s7 = lane & 7;
    uint32_t koff[4];
#pragma unroll
    for (int ks = 0; ks < 4; ks++) koff[ks] = ((ks * 2) ^ (s7 & 6)) << 4;
    const int rowA0 = wm * 32 + s7 + ((lane >> 3) & 1) * 8;
    const uint32_t aAb = rowA0 * 128 + (((((lane >> 4) & 1)) ^ (s7 & 1)) << 4);
    const int rowB0 = wn * 64 + s7 + ((lane >> 4) & 1) * 8;
    const uint32_t aBb = 16384 + rowB0 * 128 + (((((lane >> 3) & 1)) ^ (s7 & 1)) << 4);

    const int KT = K >> 6;   // >= 12 always

#define GISSUE(stg, ktile) do {                                          \
        const uint32_t so_ = (uint32_t)(stg) * 32768u;                   \
        const char* pA_ = gA + (size_t)(ktile) * 128;                    \
        const char* pB_ = gB + (size_t)(ktile) * 128;                    \
        _Pragma("unroll")                                                \
        for (int c_ = 0; c_ < 4; c_++) {                                 \
            cp16(sbase + so_ + dst[c_], pA_ + c_ * 16);                  \
            cp16(sbase + so_ + 16384 + dst[c_], pB_ + c_ * 16);          \
        }                                                                \
        asm volatile("cp.async.commit_group;\n");                        \
    } while (0)

    // prologue: stages 0 and 1 (groups 0, 1)
    GISSUE(0, 0);
    GISSUE(1, 1);

    int s_cur = 0, s_nxt = 2;
    for (int kt = 0; kt < KT; kt++) {
        if (kt < KT - 1) asm volatile("cp.async.wait_group 1;\n");
        else             asm volatile("cp.async.wait_group 0;\n");
        __syncthreads();
        // issue next tile into stage s_nxt (== stage (kt-1)%3, whose readers all
        // finished before the barrier above)
        if (kt + 2 < KT) GISSUE(s_nxt, kt + 2);

        const uint32_t so = (uint32_t)s_cur * 32768u;
#pragma unroll
        for (int ks = 0; ks < 4; ks++) {
            int a0[4], a1[4];
            ldsm4(sbase + so + aAb + koff[ks], a0);
            ldsm4(sbase + so + aAb + 2048 + koff[ks], a1);
#pragma unroll
            for (int p = 0; p < 4; p++) {
                int bf[4];
                ldsm4(sbase + so + aBb + p * 2048 + koff[ks], bf);
                mma_bf16(acc[0][2 * p],     a0, bf[0], bf[1]);
                mma_bf16(acc[1][2 * p],     a1, bf[0], bf[1]);
                mma_bf16(acc[0][2 * p + 1], a0, bf[2], bf[3]);
                mma_bf16(acc[1][2 * p + 1], a1, bf[2], bf[3]);
            }
        }
        if (++s_cur == 3) s_cur = 0;
        if (++s_nxt == 3) s_nxt = 0;
    }
#undef GISSUE

    // epilogue
    const float sa = __fdiv_rn(amax_get(amaxA, nA), 127.0f);
    const float sb = __fdiv_rn(amax_get(amaxB, nB), 127.0f);
    const float sc = sa * sb;
    float lmax = 0.0f;
#pragma unroll
    for (int mi = 0; mi < 2; mi++) {
        const int rowb = m0 + wm * 32 + mi * 16 + gid;
#pragma unroll
        for (int nj = 0; nj < 8; nj++) {
            const int col = n0 + wn * 64 + nj * 8 + 2 * tig;
            const float bi0 = bias[col], bi1 = bias[col + 1];
#pragma unroll
            for (int half = 0; half < 2; half++) {
                const int row = rowb + half * 8;
                const size_t off = (size_t)row * N + col;
                float v0 = acc[mi][nj][half * 2]     * sc + bi0;
                float v1 = acc[mi][nj][half * 2 + 1] * sc + bi1;
                if (EPI == 1) {
                    float2 rv = *reinterpret_cast<const float2*>(&res[off]);
                    v0 += rv.x; v1 += rv.y;
                }
                if (EPI == 2) {
                    v0 = 0.5f * v0 * (1.0f + erff(v0 * 0.70710678118654752440f));
                    v1 = 0.5f * v1 * (1.0f + erff(v1 * 0.70710678118654752440f));
                    lmax = fmaxf(lmax, fmaxf(fabsf(v0), fabsf(v1)));
                }
                if (EPI == 1) {
                    *reinterpret_cast<float2*>(&C[off]) = make_float2(v0, v1);
                } else {
                    // single-consumer bulk output: evict-first streaming store
                    stg_cs2(&C[off], v0, v1);
                }
            }
        }
    }
    if (EPI == 2) {
#pragma unroll
        for (int o = 16; o > 0; o >>= 1)
            lmax = fmaxf(lmax, __shfl_xor_sync(0xffffffffu, lmax, o));
        __shared__ float sred[8];
        if (lane == 0) sred[warp] = lmax;
        __syncthreads();
        if (tid == 0) {
            float t = sred[0];
#pragma unroll
            for (int k = 1; k < 8; k++) t = fmaxf(t, sred[k]);
            atomicMaxF(gmax + ((blockIdx.y * gridDim.x + blockIdx.x) & 31) * 64, t);
        }
    }
}

// ---------------- temporal attention: one block per (b, c, h) ----------------
// qkv is a single-consumer bulk stream -> evict-first loads.
__global__ __launch_bounds__(256) void attn_k(const float* __restrict__ qkv,
                                              float* __restrict__ o,
                                              float* __restrict__ slot) {
    __shared__ float sQ[64][64];   // Q, later reused for V
    __shared__ float sKt[64][64];  // K transposed + rotated: [d][(t+d)&63]
    __shared__ float sS[64][64];   // scores rotated: [t][(s+t)&63]
    int id = blockIdx.x, tid = threadIdx.x;
    int h = id % 12, c = (id / 12) & 63, b = id / (12 * 64);
    size_t base = ((size_t)(b * 4096 + c * 64)) * DQKV + h * 64;

    for (int i = tid; i < 1024; i += 256) {
        int t = i >> 4, c4 = (i & 15) * 4;
        float4 q4 = ldg_cs4(&qkv[base + (size_t)t * DQKV + c4]);
        *reinterpret_cast<float4*>(&sQ[t][c4]) = q4;
        float4 k4 = ldg_cs4(&qkv[base + (size_t)t * DQKV + 768 + c4]);
        sKt[c4 + 0][(t + c4 + 0) & 63] = k4.x;
        sKt[c4 + 1][(t + c4 + 1) & 63] = k4.y;
        sKt[c4 + 2][(t + c4 + 2) & 63] = k4.z;
        sKt[c4 + 3][(t + c4 + 3) & 63] = k4.w;
    }
    __syncthreads();

    int i4 = tid >> 4, j4 = tid & 15;
    {
        float acc[4][4];
#pragma unroll
        for (int i = 0; i < 4; i++)
#pragma unroll
            for (int j = 0; j < 4; j++) acc[i][j] = 0.0f;
#pragma unroll 4
        for (int d = 0; d < 64; d++) {
            float qa[4], kb[4];
#pragma unroll
            for (int i = 0; i < 4; i++) qa[i] = sQ[i4 * 4 + i][d];
#pragma unroll
            for (int j = 0; j < 4; j++) kb[j] = sKt[d][((j4 * 4 + j) + d) & 63];
#pragma unroll
            for (int i = 0; i < 4; i++)
#pragma unroll
                for (int j = 0; j < 4; j++) acc[i][j] = fmaf(qa[i], kb[j], acc[i][j]);
        }
#pragma unroll
        for (int i = 0; i < 4; i++) {
            int tt = i4 * 4 + i;
#pragma unroll
            for (int j = 0; j < 4; j++) {
                int ss = j4 * 4 + j;
                sS[tt][(ss + tt) & 63] = acc[i][j] * 0.125f;
            }
        }
    }
    __syncthreads();

    for (int i = tid; i < 1024; i += 256) {
        int t = i >> 4, c4 = (i & 15) * 4;
        float4 v4 = ldg_cs4(&qkv[base + (size_t)t * DQKV + 1536 + c4]);
        *reinterpret_cast<float4*>(&sQ[t][c4]) = v4;
    }
    // parallel softmax: 4 threads per row, 16 elements each; combine via shfl
    {
        int r = tid >> 2, qq = tid & 3;
        int sbeg = qq * 16;
        float m = -3.402823466e38f;
#pragma unroll
        for (int i = 0; i < 16; i++) m = fmaxf(m, sS[r][(sbeg + i + r) & 63]);
        m = fmaxf(m, __shfl_xor_sync(0xffffffffu, m, 1));
        m = fmaxf(m, __shfl_xor_sync(0xffffffffu, m, 2));
        float sum = 0.0f;
#pragma unroll
        for (int i = 0; i < 16; i++) {
            float e = expf(sS[r][(sbeg + i + r) & 63] - m);
            sS[r][(sbeg + i + r) & 63] = e;
            sum += e;
        }
        sum += __shfl_xor_sync(0xffffffffu, sum, 1);
        sum += __shfl_xor_sync(0xffffffffu, sum, 2);
        float inv = __fdiv_rn(1.0f, sum);
#pragma unroll
        for (int i = 0; i < 16; i++) sS[r][(sbeg + i + r) & 63] *= inv;
    }
    __syncthreads();

    float acc[4][4];
#pragma unroll
    for (int i = 0; i < 4; i++)
#pragma unroll
        for (int j = 0; j < 4; j++) acc[i][j] = 0.0f;
#pragma unroll 4
    for (int s = 0; s < 64; s++) {
        float pa[4], vb[4];
#pragma unroll
        for (int i = 0; i < 4; i++) { int tt = i4 * 4 + i; pa[i] = sS[tt][(s + tt) & 63]; }
#pragma unroll
        for (int j = 0; j < 4; j++) vb[j] = sQ[s][j4 * 4 + j];
#pragma unroll
        for (int i = 0; i < 4; i++)
#pragma unroll
            for (int j = 0; j < 4; j++) acc[i][j] = fmaf(pa[i], vb[j], acc[i][j]);
    }
    float lmax = 0.0f;
#pragma unroll
    for (int i = 0; i < 4; i++) {
        int tt = i4 * 4 + i;
        size_t orow = ((size_t)(b * 4096 + c * 64 + tt)) * DM + h * 64;
#pragma unroll
        for (int j = 0; j < 4; j++) {
            int dd = j4 * 4 + j;
            o[orow + dd] = acc[i][j];
            lmax = fmaxf(lmax, fabsf(acc[i][j]));
        }
    }
#pragma unroll
    for (int off = 16; off > 0; off >>= 1)
        lmax = fmaxf(lmax, __shfl_xor_sync(0xffffffffu, lmax, off));
    if ((tid & 31) == 0) atomicMaxF(slot + (blockIdx.x & 31) * 64, lmax);
}

// ---------------- launch ----------------
extern "C" void kernel_launch(void* const* d_in, const int* in_sizes, int n_in,
                              void* d_out, int out_size) {
    const float* x      = (const float*)d_in[0];
    const float* ln1_g  = (const float*)d_in[1];
    const float* ln1_b  = (const float*)d_in[2];
    const float* qkv_w  = (const float*)d_in[3];
    const float* qkv_b  = (const float*)d_in[4];
    const float* proj_w = (const float*)d_in[5];
    const float* proj_b = (const float*)d_in[6];
    const float* ln2_g  = (const float*)d_in[7];
    const float* ln2_b  = (const float*)d_in[8];
    const float* fc1_w  = (const float*)d_in[9];
    const float* fc1_b  = (const float*)d_in[10];
    const float* fc2_w  = (const float*)d_in[11];
    const float* fc2_b  = (const float*)d_in[12];

    float *pf, *pqkv, *px2, *pfc1, *pamax, *pslots;
    __nv_bfloat16 *pq, *pfc1q, *pwqkv, *pwproj, *pwfc1, *pwfc2;
    cudaGetSymbolAddress((void**)&pf,    g_f);
    cudaGetSymbolAddress((void**)&pqkv,  g_qkv);
    cudaGetSymbolAddress((void**)&px2,   g_x2);
    cudaGetSymbolAddress((void**)&pfc1,  g_fc1);
    cudaGetSymbolAddress((void**)&pq,    g_qb);
    cudaGetSymbolAddress((void**)&pfc1q, g_fc1q);
    cudaGetSymbolAddress((void**)&pwqkv, g_wqkv);
    cudaGetSymbolAddress((void**)&pwproj,g_wproj);
    cudaGetSymbolAddress((void**)&pwfc1, g_wfc1);
    cudaGetSymbolAddress((void**)&pwfc2, g_wfc2);
    cudaGetSymbolAddress((void**)&pamax, g_amax);
    cudaGetSymbolAddress((void**)&pslots,g_slots);

    const int SMEM = 3 * 32768;   // 3 stages x 32KB = 96KB
    cudaFuncSetAttribute(gemm_bf16_k<0>, cudaFuncAttributeMaxDynamicSharedMemorySize, SMEM);
    cudaFuncSetAttribute(gemm_bf16_k<1>, cudaFuncAttributeMaxDynamicSharedMemorySize, SMEM);
    cudaFuncSetAttribute(gemm_bf16_k<2>, cudaFuncAttributeMaxDynamicSharedMemorySize, SMEM);

    // fork: weight prep runs on a side stream, overlapped with ln1 + quant_a
    cudaStream_t s2;
    cudaStreamCreateWithFlags(&s2, cudaStreamNonBlocking);
    cudaEvent_t eFork, eJoin;
    cudaEventCreateWithFlags(&eFork, cudaEventDisableTiming);
    cudaEventCreateWithFlags(&eJoin, cudaEventDisableTiming);

    cudaEventRecord(eFork, 0);
    cudaStreamWaitEvent(s2, eFork, 0);
    absmax_w_k<<<dim3(512, 4), 256, 0, s2>>>(qkv_w, proj_w, fc1_w, fc2_w, pamax);
    quant_w_k<<<dim3(512, 4), 256, 0, s2>>>(qkv_w, proj_w, fc1_w, fc2_w,
                                            pwqkv, pwproj, pwfc1, pwfc2, pamax);
    cudaEventRecord(eJoin, s2);

    // attn branch (main stream, overlapped with weight prep)
    ln_k<<<NTOK, 192>>>(x, ln1_g, ln1_b, pf, pslots + 0 * 2048);
    quant_a_k<<<3072, 256>>>(pf, pq, NTOK * DM / 8, pslots + 0 * 2048);
    cudaStreamWaitEvent(0, eJoin, 0);   // join: weights ready before first GEMM
    gemm_bf16_k<0><<<dim3(DQKV / 128, NTOK / 128), 256, SMEM>>>(
        pq, pwqkv, NTOK, DQKV, DM, pslots + 0 * 2048, 32, pamax + 4, 1,
        qkv_b, nullptr, pqkv, nullptr);
    attn_k<<<8 * 64 * 12, 256>>>(pqkv, pf, pslots + 1 * 2048);
    quant_a_k<<<3072, 256>>>(pf, pq, NTOK * DM / 8, pslots + 1 * 2048);
    gemm_bf16_k<1><<<dim3(DM / 128, NTOK / 128), 256, SMEM>>>(
        pq, pwproj, NTOK, DM, DM, pslots + 1 * 2048, 32, pamax + 5, 1,
        proj_b, x, px2, nullptr);

    // mlp branch
    ln_k<<<NTOK, 192>>>(px2, ln2_g, ln2_b, pf, pslots + 2 * 2048);
    quant_a_k<<<3072, 256>>>(pf, pq, NTOK * DM / 8, pslots + 2 * 2048);
    gemm_bf16_k<2><<<dim3(DFC / 128, NTOK / 128), 256, SMEM>>>(
        pq, pwfc1, NTOK, DFC, DM, pslots + 2 * 2048, 32, pamax + 6, 1,
        fc1_b, nullptr, pfc1, pslots + 3 * 2048);
    quant_a_k<<<6144, 256>>>(pfc1, pfc1q, NTOK * DFC / 8, pslots + 3 * 2048);
    gemm_bf16_k<1><<<dim3(DM / 128, NTOK / 128), 256, SMEM>>>(
        pfc1q, pwfc2, NTOK, DM, DFC, pslots + 3 * 2048, 32, pamax + 7, 1,
        fc2_b, px2, (float*)d_out, nullptr);

    cudaStreamDestroy(s2);
    cudaEventDestroy(eFork);
    cudaEventDestroy(eJoin);
}